// round 10
// baseline (speedup 1.0000x reference)
#include <cuda_runtime.h>
#include <cuda_fp16.h>
#include <math.h>
#include <stdint.h>

// ---------------- problem constants ----------------
#define NROWS 8192      // b*n
#define CDIM  256
#define NTILES 64
#define NPAIRTILES 2080 // NTILES*(NTILES+1)/2
#define BQ    64
#define DDIM  65536
#define MARGIN 0.3f
#define FLTMAX_BITS 0x7F7FFFFF

#define NTHREADS 128               // 4 warps: 2m x 2n, 64x64 each
#define TILE_BYTES 16384           // 128 rows x 128B (64 fp16 cols)
#define STAGE_BYTES (2 * TILE_BYTES)  // A, B
#define SMEM_DYN (2 * STAGE_BYTES + 1024)
#define NDRBLK 64
#define NPREPBLK 1024              // 8 rows per block

// ---------------- device globals (no allocs allowed) ----------------
__device__ __align__(128) __half g_P[(size_t)NROWS * CDIM];
__device__ float g_sq[NROWS];
__device__ float g_hp2[NROWS];
__device__ float g_hn2[NROWS];
__device__ float g_dpart[NDRBLK];
__device__ unsigned g_done;

// ---------------- PTX helpers (baseline sm_80-class only) ----------------
__device__ __forceinline__ uint32_t smem_u32(const void* p) {
    uint32_t a;
    asm("{ .reg .u64 t; cvta.to.shared.u64 t, %1; cvt.u32.u64 %0, t; }" : "=r"(a) : "l"(p));
    return a;
}

#define CP_ASYNC16(dst, src) \
    asm volatile("cp.async.cg.shared.global [%0], [%1], 16;" :: "r"(dst), "l"(src) : "memory")
#define CP_COMMIT() asm volatile("cp.async.commit_group;" ::: "memory")

#define LDSM4(r, addr) \
    asm volatile("ldmatrix.sync.aligned.m8n8.x4.shared.b16 {%0,%1,%2,%3}, [%4];" \
        : "=r"((r)[0]), "=r"((r)[1]), "=r"((r)[2]), "=r"((r)[3]) : "r"(addr))

// fp16-accumulate MMA: D(2 regs packed half2) = A(4) x B(2) + D
#define MMA16816H(d, a, b0, b1) \
    asm volatile("mma.sync.aligned.m16n8k16.row.col.f16.f16.f16.f16 " \
        "{%0,%1}, {%2,%3,%4,%5}, {%6,%7}, {%0,%1};" \
        : "+r"((d)[0]), "+r"((d)[1]) \
        : "r"((a)[0]), "r"((a)[1]), "r"((a)[2]), "r"((a)[3]), "r"(b0), "r"(b1))

// ---------------------------------------------------------------------------
// Kernel 0 (fused): blocks [0,1024): fp16 convert + row norms (of ROUNDED
// values) + hp/hn reset. Blocks [1024,1088): dr (L1) partial sums.
// ---------------------------------------------------------------------------
__global__ void prep_kernel(const float* __restrict__ x,
                            const float* __restrict__ e0,
                            const float* __restrict__ e1,
                            const float* __restrict__ l0,
                            const float* __restrict__ l1) {
    const int tid = threadIdx.x;
    if (blockIdx.x == 0 && tid == 0) g_done = 0u;
    if (blockIdx.x < NPREPBLK) {
        const int wid = tid >> 5, lane = tid & 31;
        const int row = blockIdx.x * 8 + wid;
        const float4* xr = reinterpret_cast<const float4*>(x + (size_t)row * CDIM);
        float4 v0 = xr[lane * 2 + 0];
        float4 v1 = xr[lane * 2 + 1];
        float a[8] = {v0.x, v0.y, v0.z, v0.w, v1.x, v1.y, v1.z, v1.w};
        float s = 0.0f;
        unsigned hb[8];
#pragma unroll
        for (int i = 0; i < 8; i++) {
            __half h = __float2half_rn(a[i]);
            hb[i] = (unsigned)__half_as_ushort(h);
            float r = __half2float(h);
            s = fmaf(r, r, s);
        }
        uint4 ph = make_uint4(hb[0] | (hb[1] << 16), hb[2] | (hb[3] << 16),
                              hb[4] | (hb[5] << 16), hb[6] | (hb[7] << 16));
        *reinterpret_cast<uint4*>(&g_P[(size_t)row * CDIM + lane * 8]) = ph;
#pragma unroll
        for (int off = 16; off > 0; off >>= 1)
            s += __shfl_xor_sync(0xFFFFFFFFu, s, off);
        if (lane == 0) {
            g_sq[row]  = s;
            g_hp2[row] = 0.0f;
            g_hn2[row] = __int_as_float(FLTMAX_BITS);
        }
    } else {
        __shared__ float red[256];
        const int b = blockIdx.x - NPREPBLK;
        const int base = b * (DDIM / NDRBLK);
        float s = 0.0f;
#pragma unroll
        for (int k = 0; k < DDIM / NDRBLK / 256; k++) {
            int i = base + k * 256 + tid;
            s += fabsf(e0[i] - l0[i]) + fabsf(e1[i] - l1[i]);
        }
        red[tid] = s;
        __syncthreads();
        for (int st = 128; st > 0; st >>= 1) {
            if (tid < st) red[tid] += red[tid + st];
            __syncthreads();
        }
        if (tid == 0) g_dpart[b] = red[0];
    }
}

// ---------------------------------------------------------------------------
// Load one 64-col chunk kc into a stage: A (rows iBase..), B (rows jBase..).
// 128 threads x 16 cp.async x 16B, SW128 swizzle.
// ---------------------------------------------------------------------------
__device__ __forceinline__ void load_chunk(uint32_t stage, int iBase, int jBase,
                                           int kc, int tid) {
    const int cu = tid & 7;          // 16B column unit
    const int r0 = tid >> 3;         // 0..15
    const uint32_t colsw = ((uint32_t)(cu * 16)) ^ (((uint32_t)(r0 & 7)) << 4);
    const int ecol = kc * 64 + cu * 8;
#pragma unroll
    for (int i = 0; i < 8; i++) {
        const int row = r0 + 16 * i;
        const uint32_t dst = stage + (uint32_t)row * 128u + colsw;
        CP_ASYNC16(dst,              &g_P[(size_t)(iBase + row) * CDIM + ecol]); // A
        CP_ASYNC16(dst + TILE_BYTES, &g_P[(size_t)(jBase + row) * CDIM + ecol]); // B
    }
    CP_COMMIT();
}

// ---------------------------------------------------------------------------
// Kernel 1: warp-MMA fused Gram + mining, one 128x128 tile (it<=jt) per CTA.
// 4 warps (2m x 2n), 64x64 warp tile, fp16 MMA with fp16 accumulators.
// 3 CTAs/SM. Last CTA performs the final scalar reduction.
// ---------------------------------------------------------------------------
__global__ void __launch_bounds__(NTHREADS, 3)
pair_mma_kernel(const float* __restrict__ gt,
                const float* __restrict__ s0,
                const float* __restrict__ s1,
                const float* __restrict__ s2,
                float* __restrict__ out) {
    extern __shared__ __align__(16) char dsm[];
    __shared__ float s_sqi[128], s_sqj[128], s_diag[128];
    __shared__ int s_rowmin[128], s_colmin[128];
    __shared__ float s_red[NTHREADS];
    __shared__ unsigned s_last;

    const int tid = threadIdx.x;
    const int wid = tid >> 5;
    const int lane = tid & 31;
    const int wm = wid & 1;          // 2 warps along m (64 rows each)
    const int wn = wid >> 1;         // 2 warps along n (64 cols each)
    const int lrow = lane & 15;
    const int lcolb = (lane >> 4) * 16;
    const uint32_t lxor = ((uint32_t)(lrow & 7)) << 4;
    const int groupId = lane >> 2;
    const int tid4 = lane & 3;
    const float INFV = __int_as_float(0x7F800000);

    // triangular tile decode
    int t = blockIdx.x;
    int it = (int)floorf((129.0f - sqrtf(129.0f * 129.0f - 8.0f * (float)t)) * 0.5f);
    while (it > 0 && (it * (129 - it)) / 2 > t) it--;
    while (((it + 1) * (129 - (it + 1))) / 2 <= t) it++;
    const int jt = it + (t - (it * (129 - it)) / 2);
    const int iBase = it * 128;
    const int jBase = jt * 128;
    const bool dtile = (it == jt);

    const uint32_t sb = smem_u32(dsm);
    const uint32_t stage0 = (sb + 1023u) & ~1023u;
    const uint32_t stage1 = stage0 + STAGE_BYTES;

    if (tid < 128) {
        s_sqi[tid] = g_sq[iBase + tid];
        s_sqj[tid] = g_sq[jBase + tid];
        s_rowmin[tid] = FLTMAX_BITS;
        s_colmin[tid] = FLTMAX_BITS;
    }

    // fp16 accumulators: acc[mf][nf] = 2 regs (packed half2)
    uint32_t acc[4][8][2];
#pragma unroll
    for (int mf = 0; mf < 4; mf++)
#pragma unroll
        for (int nf = 0; nf < 8; nf++) { acc[mf][nf][0] = 0u; acc[mf][nf][1] = 0u; }

    load_chunk(stage0, iBase, jBase, 0, tid);
    load_chunk(stage1, iBase, jBase, 1, tid);

#pragma unroll 1
    for (int kc = 0; kc < 4; kc++) {
        const uint32_t stage = (kc & 1) ? stage1 : stage0;
        if (kc < 3) asm volatile("cp.async.wait_group 1;" ::: "memory");
        else        asm volatile("cp.async.wait_group 0;" ::: "memory");
        __syncthreads();

        const uint32_t aB = stage + (uint32_t)(wm * 64 + lrow) * 128u;
        const uint32_t bB = stage + (uint32_t)TILE_BYTES
                          + (uint32_t)(wn * 64 + lrow) * 128u;

#pragma unroll
        for (int ks = 0; ks < 4; ks++) {
            const uint32_t csw = ((uint32_t)(ks * 32 + lcolb)) ^ lxor;
            uint32_t br[4][4];
#pragma unroll
            for (int ng = 0; ng < 4; ng++)
                LDSM4(br[ng], bB + (uint32_t)(ng * 16 * 128) + csw);
#pragma unroll
            for (int mf = 0; mf < 4; mf++) {
                uint32_t af[4];
                LDSM4(af, aB + (uint32_t)(mf * 16 * 128) + csw);
#pragma unroll
                for (int ng = 0; ng < 4; ng++) {
                    MMA16816H(acc[mf][2 * ng],     af, br[ng][0], br[ng][2]);
                    MMA16816H(acc[mf][2 * ng + 1], af, br[ng][1], br[ng][3]);
                }
            }
        }
        __syncthreads();
        if (kc + 2 < 4)
            load_chunk(stage, iBase, jBase, kc + 2, tid);
    }

    // ---------------- mining epilogue ----------------
    float rmin[4][2];    // [mf][rowhalf]
    float cmin[8][2];    // [nf][colparity]
#pragma unroll
    for (int mf = 0; mf < 4; mf++) { rmin[mf][0] = INFV; rmin[mf][1] = INFV; }
#pragma unroll
    for (int nf = 0; nf < 8; nf++) { cmin[nf][0] = INFV; cmin[nf][1] = INFV; }

#pragma unroll
    for (int mf = 0; mf < 4; mf++) {
#pragma unroll
        for (int nf = 0; nf < 8; nf++) {
            // unpack: reg0 = cols (tid4*2, tid4*2+1) at row groupId,
            //         reg1 = same cols at row groupId+8
            float2 h0 = __half22float2(*reinterpret_cast<__half2*>(&acc[mf][nf][0]));
            float2 h1 = __half22float2(*reinterpret_cast<__half2*>(&acc[mf][nf][1]));
            float dots[4] = {h0.x, h0.y, h1.x, h1.y};
#pragma unroll
            for (int r = 0; r < 4; r++) {
                const int row_l = wm * 64 + mf * 16 + groupId + (r >> 1) * 8;
                const int col_l = wn * 64 + nf * 8 + tid4 * 2 + (r & 1);
                float d2 = fmaf(dots[r], -2.0f, s_sqi[row_l]) + s_sqj[col_l];
                if (row_l == col_l) {
                    s_diag[row_l] = fmaxf(d2, 0.0f);
                } else {
                    rmin[mf][r >> 1] = fminf(rmin[mf][r >> 1], d2);
                    cmin[nf][r & 1]  = fminf(cmin[nf][r & 1], d2);
                }
            }
        }
    }

    // row reduce over tid4 (lanes sharing rows)
#pragma unroll
    for (int mf = 0; mf < 4; mf++) {
#pragma unroll
        for (int h = 0; h < 2; h++) {
            float v = rmin[mf][h];
            v = fminf(v, __shfl_xor_sync(0xFFFFFFFFu, v, 1));
            v = fminf(v, __shfl_xor_sync(0xFFFFFFFFu, v, 2));
            if (tid4 == 0)
                atomicMin(&s_rowmin[wm * 64 + mf * 16 + groupId + 8 * h], __float_as_int(v));
        }
    }
    // col reduce over groupId (lanes sharing cols)
#pragma unroll
    for (int nf = 0; nf < 8; nf++) {
#pragma unroll
        for (int par = 0; par < 2; par++) {
            float v = cmin[nf][par];
            v = fminf(v, __shfl_xor_sync(0xFFFFFFFFu, v, 4));
            v = fminf(v, __shfl_xor_sync(0xFFFFFFFFu, v, 8));
            v = fminf(v, __shfl_xor_sync(0xFFFFFFFFu, v, 16));
            if (groupId == 0)
                atomicMin(&s_colmin[wn * 64 + nf * 8 + tid4 * 2 + par], __float_as_int(v));
        }
    }
    __syncthreads();

    if (tid < 128) {
        const int row = iBase + tid;
        atomicMin(reinterpret_cast<int*>(&g_hn2[row]), s_rowmin[tid]);
        if (!dtile) {
            const int col = jBase + tid;
            atomicMin(reinterpret_cast<int*>(&g_hn2[col]), s_colmin[tid]);
            const int db = __float_as_int(s_diag[tid]);
            atomicMax(reinterpret_cast<int*>(&g_hp2[row]), db);
            atomicMax(reinterpret_cast<int*>(&g_hp2[col]), db);
        }
    }

    // ---- last CTA does the final reduction ----
    __threadfence();
    __syncthreads();
    if (tid == 0)
        s_last = (atomicAdd(&g_done, 1u) == NPAIRTILES - 1) ? 1u : 0u;
    __syncthreads();
    if (s_last) {
        __threadfence();
        float tsum = 0.0f;
        for (int i = tid; i < NROWS; i += NTHREADS) {
            float hp = sqrtf(fmaxf(g_hp2[i], 0.0f));
            float hn = sqrtf(fmaxf(g_hn2[i], 0.0f));
            tsum += fmaxf(hp - hn + MARGIN, 0.0f);
        }
        float msum = 0.0f;
        if (tid < BQ) {
            float g = gt[tid];
            float a = s0[tid] - g, b = s1[tid] - g, c = s2[tid] - g;
            msum = a * a + b * b + c * c;
        }
        float dsum = (tid < NDRBLK) ? g_dpart[tid] : 0.0f;

        float vals[3] = {tsum, msum, dsum};
        float res[3];
#pragma unroll
        for (int v = 0; v < 3; v++) {
            s_red[tid] = vals[v];
            __syncthreads();
            for (int st = NTHREADS / 2; st > 0; st >>= 1) {
                if (tid < st) s_red[tid] += s_red[tid + st];
                __syncthreads();
            }
            res[v] = s_red[0];
            __syncthreads();
        }
        if (tid == 0) {
            float t_loss = res[0] / (float)NROWS;
            float mse    = res[1] / (float)(BQ * 3);
            float dr     = res[2] / (float)DDIM;
            out[0] = dr + t_loss + mse;
        }
    }
}

// ---------------------------------------------------------------------------
extern "C" void kernel_launch(void* const* d_in, const int* in_sizes, int n_in,
                              void* d_out, int out_size) {
    const float* feat = (const float*)d_in[0];
    const float* gt   = (const float*)d_in[1];
    const float* s0   = (const float*)d_in[2];
    const float* s1   = (const float*)d_in[3];
    const float* s2   = (const float*)d_in[4];
    const float* e0   = (const float*)d_in[5];
    const float* e1   = (const float*)d_in[6];
    const float* l0   = (const float*)d_in[7];
    const float* l1   = (const float*)d_in[8];
    float* out = (float*)d_out;

    cudaFuncSetAttribute(pair_mma_kernel,
                         cudaFuncAttributeMaxDynamicSharedMemorySize, SMEM_DYN);

    prep_kernel<<<NPREPBLK + NDRBLK, 256>>>(feat, e0, e1, l0, l1);
    pair_mma_kernel<<<NPAIRTILES, NTHREADS, SMEM_DYN>>>(gt, s0, s1, s2, out);
}

// round 11
// speedup vs baseline: 1.1654x; 1.1654x over previous
#include <cuda_runtime.h>
#include <cuda_fp16.h>
#include <math.h>
#include <stdint.h>

// ---------------- problem constants ----------------
#define NROWS 8192      // b*n
#define CDIM  256
#define NTILES 64
#define NPAIRTILES 2080 // NTILES*(NTILES+1)/2
#define BQ    64
#define DDIM  65536
#define MARGIN 0.3f
#define FLTMAX_BITS 0x7F7FFFFF

#define NTHREADS 256               // 8 warps: 4 along m x 2 along n, 32x64 each
#define TILE_BYTES 16384           // 128 rows x 128B (64 fp16 cols)
#define STAGE_BYTES (2 * TILE_BYTES)  // A, B
#define SMEM_DYN (2 * STAGE_BYTES + 1024)
#define NDRBLK 64
#define NPREPBLK 1024              // 8 rows per block

// ---------------- device globals (no allocs allowed) ----------------
__device__ __align__(128) __half g_P[(size_t)NROWS * CDIM];
__device__ float g_sq[NROWS];
__device__ float g_hp2[NROWS];
__device__ float g_hn2[NROWS];
__device__ float g_dpart[NDRBLK];
__device__ unsigned g_done;

// ---------------- PTX helpers (baseline sm_80-class only) ----------------
__device__ __forceinline__ uint32_t smem_u32(const void* p) {
    uint32_t a;
    asm("{ .reg .u64 t; cvta.to.shared.u64 t, %1; cvt.u32.u64 %0, t; }" : "=r"(a) : "l"(p));
    return a;
}

#define CP_ASYNC16(dst, src) \
    asm volatile("cp.async.cg.shared.global [%0], [%1], 16;" :: "r"(dst), "l"(src) : "memory")
#define CP_COMMIT() asm volatile("cp.async.commit_group;" ::: "memory")

#define LDSM4(r, addr) \
    asm volatile("ldmatrix.sync.aligned.m8n8.x4.shared.b16 {%0,%1,%2,%3}, [%4];" \
        : "=r"((r)[0]), "=r"((r)[1]), "=r"((r)[2]), "=r"((r)[3]) : "r"(addr))

// fp16-accumulate MMA: D(2 regs packed half2) = A(4) x B(2) + D
#define MMA16816H(d, a, b0, b1) \
    asm volatile("mma.sync.aligned.m16n8k16.row.col.f16.f16.f16.f16 " \
        "{%0,%1}, {%2,%3,%4,%5}, {%6,%7}, {%0,%1};" \
        : "+r"((d)[0]), "+r"((d)[1]) \
        : "r"((a)[0]), "r"((a)[1]), "r"((a)[2]), "r"((a)[3]), "r"(b0), "r"(b1))

// ---------------------------------------------------------------------------
// Kernel 0 (fused): blocks [0,1024): fp16 convert + row norms (of ROUNDED
// values) + hp/hn reset. Blocks [1024,1088): dr (L1) partial sums.
// ---------------------------------------------------------------------------
__global__ void prep_kernel(const float* __restrict__ x,
                            const float* __restrict__ e0,
                            const float* __restrict__ e1,
                            const float* __restrict__ l0,
                            const float* __restrict__ l1) {
    const int tid = threadIdx.x;
    if (blockIdx.x == 0 && tid == 0) g_done = 0u;
    if (blockIdx.x < NPREPBLK) {
        const int wid = tid >> 5, lane = tid & 31;
        const int row = blockIdx.x * 8 + wid;
        const float4* xr = reinterpret_cast<const float4*>(x + (size_t)row * CDIM);
        float4 v0 = xr[lane * 2 + 0];
        float4 v1 = xr[lane * 2 + 1];
        float a[8] = {v0.x, v0.y, v0.z, v0.w, v1.x, v1.y, v1.z, v1.w};
        float s = 0.0f;
        unsigned hb[8];
#pragma unroll
        for (int i = 0; i < 8; i++) {
            __half h = __float2half_rn(a[i]);
            hb[i] = (unsigned)__half_as_ushort(h);
            float r = __half2float(h);
            s = fmaf(r, r, s);
        }
        uint4 ph = make_uint4(hb[0] | (hb[1] << 16), hb[2] | (hb[3] << 16),
                              hb[4] | (hb[5] << 16), hb[6] | (hb[7] << 16));
        *reinterpret_cast<uint4*>(&g_P[(size_t)row * CDIM + lane * 8]) = ph;
#pragma unroll
        for (int off = 16; off > 0; off >>= 1)
            s += __shfl_xor_sync(0xFFFFFFFFu, s, off);
        if (lane == 0) {
            g_sq[row]  = s;
            g_hp2[row] = 0.0f;
            g_hn2[row] = __int_as_float(FLTMAX_BITS);
        }
    } else {
        __shared__ float red[256];
        const int b = blockIdx.x - NPREPBLK;
        const int base = b * (DDIM / NDRBLK);
        float s = 0.0f;
#pragma unroll
        for (int k = 0; k < DDIM / NDRBLK / 256; k++) {
            int i = base + k * 256 + tid;
            s += fabsf(e0[i] - l0[i]) + fabsf(e1[i] - l1[i]);
        }
        red[tid] = s;
        __syncthreads();
        for (int st = 128; st > 0; st >>= 1) {
            if (tid < st) red[tid] += red[tid + st];
            __syncthreads();
        }
        if (tid == 0) g_dpart[b] = red[0];
    }
}

// ---------------------------------------------------------------------------
// Load one 64-col chunk kc into a stage: A (rows iBase..), B (rows jBase..).
// 256 threads x 8 cp.async x 16B, SW128 swizzle.
// ---------------------------------------------------------------------------
__device__ __forceinline__ void load_chunk(uint32_t stage, int iBase, int jBase,
                                           int kc, int tid) {
    const int cu = tid & 7;          // 16B column unit
    const int r0 = tid >> 3;         // 0..31
    const uint32_t colsw = ((uint32_t)(cu * 16)) ^ (((uint32_t)(r0 & 7)) << 4);
    const int ecol = kc * 64 + cu * 8;
#pragma unroll
    for (int i = 0; i < 4; i++) {
        const int row = r0 + 32 * i;
        const uint32_t dst = stage + (uint32_t)row * 128u + colsw;
        CP_ASYNC16(dst,              &g_P[(size_t)(iBase + row) * CDIM + ecol]); // A
        CP_ASYNC16(dst + TILE_BYTES, &g_P[(size_t)(jBase + row) * CDIM + ecol]); // B
    }
    CP_COMMIT();
}

// ---------------------------------------------------------------------------
// Kernel 1: warp-MMA fused Gram + mining, one 128x128 tile (it<=jt) per CTA.
// 8 warps (4m x 2n), 32x64 warp tile, fp16 MMA with fp16 accumulators.
// launch_bounds(256,3) -> 3 CTAs/SM, 24 warps/SM.
// Last CTA performs the final scalar reduction.
// ---------------------------------------------------------------------------
__global__ void __launch_bounds__(NTHREADS, 3)
pair_mma_kernel(const float* __restrict__ gt,
                const float* __restrict__ s0,
                const float* __restrict__ s1,
                const float* __restrict__ s2,
                float* __restrict__ out) {
    extern __shared__ __align__(16) char dsm[];
    __shared__ float s_sqi[128], s_sqj[128], s_diag[128];
    __shared__ int s_rowmin[128], s_colmin[128];
    __shared__ float s_red[NTHREADS];
    __shared__ unsigned s_last;

    const int tid = threadIdx.x;
    const int wid = tid >> 5;
    const int lane = tid & 31;
    const int wm = wid & 3;          // 4 warps along m (32 rows each)
    const int wn = wid >> 2;         // 2 warps along n (64 cols each)
    const int lrow = lane & 15;
    const int lcolb = (lane >> 4) * 16;
    const uint32_t lxor = ((uint32_t)(lrow & 7)) << 4;
    const int groupId = lane >> 2;
    const int tid4 = lane & 3;
    const float INFV = __int_as_float(0x7F800000);

    // triangular tile decode
    int t = blockIdx.x;
    int it = (int)floorf((129.0f - sqrtf(129.0f * 129.0f - 8.0f * (float)t)) * 0.5f);
    while (it > 0 && (it * (129 - it)) / 2 > t) it--;
    while (((it + 1) * (129 - (it + 1))) / 2 <= t) it++;
    const int jt = it + (t - (it * (129 - it)) / 2);
    const int iBase = it * 128;
    const int jBase = jt * 128;
    const bool dtile = (it == jt);

    const uint32_t sb = smem_u32(dsm);
    const uint32_t stage0 = (sb + 1023u) & ~1023u;
    const uint32_t stage1 = stage0 + STAGE_BYTES;

    if (tid < 128) {
        s_sqi[tid] = g_sq[iBase + tid];
        s_sqj[tid] = g_sq[jBase + tid];
        s_rowmin[tid] = FLTMAX_BITS;
        s_colmin[tid] = FLTMAX_BITS;
    }

    // fp16 accumulators: acc[mf][nf] = 2 regs (packed half2)
    uint32_t acc[2][8][2];
#pragma unroll
    for (int mf = 0; mf < 2; mf++)
#pragma unroll
        for (int nf = 0; nf < 8; nf++) { acc[mf][nf][0] = 0u; acc[mf][nf][1] = 0u; }

    load_chunk(stage0, iBase, jBase, 0, tid);
    load_chunk(stage1, iBase, jBase, 1, tid);

#pragma unroll 1
    for (int kc = 0; kc < 4; kc++) {
        const uint32_t stage = (kc & 1) ? stage1 : stage0;
        if (kc < 3) asm volatile("cp.async.wait_group 1;" ::: "memory");
        else        asm volatile("cp.async.wait_group 0;" ::: "memory");
        __syncthreads();

        const uint32_t aB = stage + (uint32_t)(wm * 32 + lrow) * 128u;
        const uint32_t bB = stage + (uint32_t)TILE_BYTES
                          + (uint32_t)(wn * 64 + lrow) * 128u;

#pragma unroll
        for (int ks = 0; ks < 4; ks++) {
            const uint32_t csw = ((uint32_t)(ks * 32 + lcolb)) ^ lxor;
            uint32_t br[4][4];
#pragma unroll
            for (int ng = 0; ng < 4; ng++)
                LDSM4(br[ng], bB + (uint32_t)(ng * 16 * 128) + csw);
#pragma unroll
            for (int mf = 0; mf < 2; mf++) {
                uint32_t af[4];
                LDSM4(af, aB + (uint32_t)(mf * 16 * 128) + csw);
#pragma unroll
                for (int ng = 0; ng < 4; ng++) {
                    MMA16816H(acc[mf][2 * ng],     af, br[ng][0], br[ng][2]);
                    MMA16816H(acc[mf][2 * ng + 1], af, br[ng][1], br[ng][3]);
                }
            }
        }
        __syncthreads();
        if (kc + 2 < 4)
            load_chunk(stage, iBase, jBase, kc + 2, tid);
    }

    // ---------------- mining epilogue ----------------
    float rmin[2][2];    // [mf][rowhalf]
    float cmin[8][2];    // [nf][colparity]
#pragma unroll
    for (int mf = 0; mf < 2; mf++) { rmin[mf][0] = INFV; rmin[mf][1] = INFV; }
#pragma unroll
    for (int nf = 0; nf < 8; nf++) { cmin[nf][0] = INFV; cmin[nf][1] = INFV; }

#pragma unroll
    for (int mf = 0; mf < 2; mf++) {
#pragma unroll
        for (int nf = 0; nf < 8; nf++) {
            float2 h0 = __half22float2(*reinterpret_cast<__half2*>(&acc[mf][nf][0]));
            float2 h1 = __half22float2(*reinterpret_cast<__half2*>(&acc[mf][nf][1]));
            float dots[4] = {h0.x, h0.y, h1.x, h1.y};
#pragma unroll
            for (int r = 0; r < 4; r++) {
                const int row_l = wm * 32 + mf * 16 + groupId + (r >> 1) * 8;
                const int col_l = wn * 64 + nf * 8 + tid4 * 2 + (r & 1);
                float d2 = fmaf(dots[r], -2.0f, s_sqi[row_l]) + s_sqj[col_l];
                if (row_l == col_l) {
                    s_diag[row_l] = fmaxf(d2, 0.0f);
                } else {
                    rmin[mf][r >> 1] = fminf(rmin[mf][r >> 1], d2);
                    cmin[nf][r & 1]  = fminf(cmin[nf][r & 1], d2);
                }
            }
        }
    }

    // row reduce over tid4 (lanes sharing rows)
#pragma unroll
    for (int mf = 0; mf < 2; mf++) {
#pragma unroll
        for (int h = 0; h < 2; h++) {
            float v = rmin[mf][h];
            v = fminf(v, __shfl_xor_sync(0xFFFFFFFFu, v, 1));
            v = fminf(v, __shfl_xor_sync(0xFFFFFFFFu, v, 2));
            if (tid4 == 0)
                atomicMin(&s_rowmin[wm * 32 + mf * 16 + groupId + 8 * h], __float_as_int(v));
        }
    }
    // col reduce over groupId (lanes sharing cols)
#pragma unroll
    for (int nf = 0; nf < 8; nf++) {
#pragma unroll
        for (int par = 0; par < 2; par++) {
            float v = cmin[nf][par];
            v = fminf(v, __shfl_xor_sync(0xFFFFFFFFu, v, 4));
            v = fminf(v, __shfl_xor_sync(0xFFFFFFFFu, v, 8));
            v = fminf(v, __shfl_xor_sync(0xFFFFFFFFu, v, 16));
            if (groupId == 0)
                atomicMin(&s_colmin[wn * 64 + nf * 8 + tid4 * 2 + par], __float_as_int(v));
        }
    }
    __syncthreads();

    if (tid < 128) {
        const int row = iBase + tid;
        atomicMin(reinterpret_cast<int*>(&g_hn2[row]), s_rowmin[tid]);
        if (!dtile) {
            const int col = jBase + tid;
            atomicMin(reinterpret_cast<int*>(&g_hn2[col]), s_colmin[tid]);
            const int db = __float_as_int(s_diag[tid]);
            atomicMax(reinterpret_cast<int*>(&g_hp2[row]), db);
            atomicMax(reinterpret_cast<int*>(&g_hp2[col]), db);
        }
    }

    // ---- last CTA does the final reduction ----
    __threadfence();
    __syncthreads();
    if (tid == 0)
        s_last = (atomicAdd(&g_done, 1u) == NPAIRTILES - 1) ? 1u : 0u;
    __syncthreads();
    if (s_last) {
        __threadfence();
        float tsum = 0.0f;
        for (int i = tid; i < NROWS; i += NTHREADS) {
            float hp = sqrtf(fmaxf(g_hp2[i], 0.0f));
            float hn = sqrtf(fmaxf(g_hn2[i], 0.0f));
            tsum += fmaxf(hp - hn + MARGIN, 0.0f);
        }
        float msum = 0.0f;
        if (tid < BQ) {
            float g = gt[tid];
            float a = s0[tid] - g, b = s1[tid] - g, c = s2[tid] - g;
            msum = a * a + b * b + c * c;
        }
        float dsum = (tid < NDRBLK) ? g_dpart[tid] : 0.0f;

        float vals[3] = {tsum, msum, dsum};
        float res[3];
#pragma unroll
        for (int v = 0; v < 3; v++) {
            s_red[tid] = vals[v];
            __syncthreads();
            for (int st = NTHREADS / 2; st > 0; st >>= 1) {
                if (tid < st) s_red[tid] += s_red[tid + st];
                __syncthreads();
            }
            res[v] = s_red[0];
            __syncthreads();
        }
        if (tid == 0) {
            float t_loss = res[0] / (float)NROWS;
            float mse    = res[1] / (float)(BQ * 3);
            float dr     = res[2] / (float)DDIM;
            out[0] = dr + t_loss + mse;
        }
    }
}

// ---------------------------------------------------------------------------
extern "C" void kernel_launch(void* const* d_in, const int* in_sizes, int n_in,
                              void* d_out, int out_size) {
    const float* feat = (const float*)d_in[0];
    const float* gt   = (const float*)d_in[1];
    const float* s0   = (const float*)d_in[2];
    const float* s1   = (const float*)d_in[3];
    const float* s2   = (const float*)d_in[4];
    const float* e0   = (const float*)d_in[5];
    const float* e1   = (const float*)d_in[6];
    const float* l0   = (const float*)d_in[7];
    const float* l1   = (const float*)d_in[8];
    float* out = (float*)d_out;

    cudaFuncSetAttribute(pair_mma_kernel,
                         cudaFuncAttributeMaxDynamicSharedMemorySize, SMEM_DYN);

    prep_kernel<<<NPREPBLK + NDRBLK, 256>>>(feat, e0, e1, l0, l1);
    pair_mma_kernel<<<NPAIRTILES, NTHREADS, SMEM_DYN>>>(gt, s0, s1, s2, out);
}

// round 13
// speedup vs baseline: 1.1840x; 1.0159x over previous
#include <cuda_runtime.h>
#include <cuda_fp16.h>
#include <math.h>
#include <stdint.h>

// ---------------- problem constants ----------------
#define NROWS 8192      // b*n
#define CDIM  256
#define NTILES 64
#define NPAIRTILES 2080 // NTILES*(NTILES+1)/2
#define BQ    64
#define DDIM  65536
#define MARGIN 0.3f
#define FLTMAX_BITS 0x7F7FFFFF

#define NTHREADS 256               // 8 warps: 4 along m x 2 along n, 32x64 each
#define TILE_BYTES 16384           // 128 rows x 128B (64 fp16 cols)
#define STAGE_BYTES (2 * TILE_BYTES)  // A, B
#define SMEM_DYN (2 * STAGE_BYTES + 1024)
#define NDRBLK 64
#define NPREPBLK 1024              // 8 rows per block

// ---------------- device globals (no allocs allowed) ----------------
__device__ __align__(128) __half g_P[(size_t)NROWS * CDIM];
__device__ float g_sq[NROWS];
__device__ float g_hp2[NROWS];
__device__ float g_hn2[NROWS];
__device__ float g_dpart[NDRBLK];
__device__ unsigned g_done;

// ---------------- PTX helpers (baseline sm_80-class only) ----------------
__device__ __forceinline__ uint32_t smem_u32(const void* p) {
    uint32_t a;
    asm("{ .reg .u64 t; cvta.to.shared.u64 t, %1; cvt.u32.u64 %0, t; }" : "=r"(a) : "l"(p));
    return a;
}

#define CP_ASYNC16(dst, src) \
    asm volatile("cp.async.cg.shared.global [%0], [%1], 16;" :: "r"(dst), "l"(src) : "memory")
#define CP_COMMIT() asm volatile("cp.async.commit_group;" ::: "memory")

#define LDSM4(r, addr) \
    asm volatile("ldmatrix.sync.aligned.m8n8.x4.shared.b16 {%0,%1,%2,%3}, [%4];" \
        : "=r"((r)[0]), "=r"((r)[1]), "=r"((r)[2]), "=r"((r)[3]) : "r"(addr))

// fp16-accumulate MMA: D(2 regs packed half2) = A(4) x B(2) + D
#define MMA16816H(d, a, b0, b1) \
    asm volatile("mma.sync.aligned.m16n8k16.row.col.f16.f16.f16.f16 " \
        "{%0,%1}, {%2,%3,%4,%5}, {%6,%7}, {%0,%1};" \
        : "+r"((d)[0]), "+r"((d)[1]) \
        : "r"((a)[0]), "r"((a)[1]), "r"((a)[2]), "r"((a)[3]), "r"(b0), "r"(b1))

// ---------------------------------------------------------------------------
// Kernel 0 (fused): blocks [0,1024): fp16 convert + row norms (of ROUNDED
// values) + hp/hn reset. Blocks [1024,1088): dr (L1) partial sums.
// ---------------------------------------------------------------------------
__global__ void prep_kernel(const float* __restrict__ x,
                            const float* __restrict__ e0,
                            const float* __restrict__ e1,
                            const float* __restrict__ l0,
                            const float* __restrict__ l1) {
    const int tid = threadIdx.x;
    if (blockIdx.x == 0 && tid == 0) g_done = 0u;
    if (blockIdx.x < NPREPBLK) {
        const int wid = tid >> 5, lane = tid & 31;
        const int row = blockIdx.x * 8 + wid;
        const float4* xr = reinterpret_cast<const float4*>(x + (size_t)row * CDIM);
        float4 v0 = xr[lane * 2 + 0];
        float4 v1 = xr[lane * 2 + 1];
        float a[8] = {v0.x, v0.y, v0.z, v0.w, v1.x, v1.y, v1.z, v1.w};
        float s = 0.0f;
        unsigned hb[8];
#pragma unroll
        for (int i = 0; i < 8; i++) {
            __half h = __float2half_rn(a[i]);
            hb[i] = (unsigned)__half_as_ushort(h);
            float r = __half2float(h);
            s = fmaf(r, r, s);
        }
        uint4 ph = make_uint4(hb[0] | (hb[1] << 16), hb[2] | (hb[3] << 16),
                              hb[4] | (hb[5] << 16), hb[6] | (hb[7] << 16));
        *reinterpret_cast<uint4*>(&g_P[(size_t)row * CDIM + lane * 8]) = ph;
#pragma unroll
        for (int off = 16; off > 0; off >>= 1)
            s += __shfl_xor_sync(0xFFFFFFFFu, s, off);
        if (lane == 0) {
            g_sq[row]  = s;
            g_hp2[row] = 0.0f;
            g_hn2[row] = __int_as_float(FLTMAX_BITS);
        }
    } else {
        __shared__ float red[256];
        const int b = blockIdx.x - NPREPBLK;
        const int base = b * (DDIM / NDRBLK);
        float s = 0.0f;
#pragma unroll
        for (int k = 0; k < DDIM / NDRBLK / 256; k++) {
            int i = base + k * 256 + tid;
            s += fabsf(e0[i] - l0[i]) + fabsf(e1[i] - l1[i]);
        }
        red[tid] = s;
        __syncthreads();
        for (int st = 128; st > 0; st >>= 1) {
            if (tid < st) red[tid] += red[tid + st];
            __syncthreads();
        }
        if (tid == 0) g_dpart[b] = red[0];
    }
}

// ---------------------------------------------------------------------------
// Load one 64-col chunk kc into a stage: A (rows iBase..), B (rows jBase..).
// 256 threads x 8 cp.async x 16B, SW128 swizzle.
// ---------------------------------------------------------------------------
__device__ __forceinline__ void load_chunk(uint32_t stage, int iBase, int jBase,
                                           int kc, int tid) {
    const int cu = tid & 7;          // 16B column unit
    const int r0 = tid >> 3;         // 0..31
    const uint32_t colsw = ((uint32_t)(cu * 16)) ^ (((uint32_t)(r0 & 7)) << 4);
    const int ecol = kc * 64 + cu * 8;
#pragma unroll
    for (int i = 0; i < 4; i++) {
        const int row = r0 + 32 * i;
        const uint32_t dst = stage + (uint32_t)row * 128u + colsw;
        CP_ASYNC16(dst,              &g_P[(size_t)(iBase + row) * CDIM + ecol]); // A
        CP_ASYNC16(dst + TILE_BYTES, &g_P[(size_t)(jBase + row) * CDIM + ecol]); // B
    }
    CP_COMMIT();
}

// ---------------------------------------------------------------------------
// Kernel 1: warp-MMA fused Gram + mining, one 128x128 tile (it<=jt) per CTA.
// 8 warps (4m x 2n), 32x64 warp tile, fp16 MMA with fp16 accumulators.
// 3 CTAs/SM. R11 sync skeleton (wait -> barrier -> compute -> barrier -> load)
// + double-banked B fragments (LDSM software pipeline over ks).
// Last CTA performs the final scalar reduction.
// ---------------------------------------------------------------------------
__global__ void __launch_bounds__(NTHREADS, 3)
pair_mma_kernel(const float* __restrict__ gt,
                const float* __restrict__ s0,
                const float* __restrict__ s1,
                const float* __restrict__ s2,
                float* __restrict__ out) {
    extern __shared__ __align__(16) char dsm[];
    __shared__ float s_sqi[128], s_sqj[128], s_diag[128];
    __shared__ int s_rowmin[128], s_colmin[128];
    __shared__ float s_red[NTHREADS];
    __shared__ unsigned s_last;

    const int tid = threadIdx.x;
    const int wid = tid >> 5;
    const int lane = tid & 31;
    const int wm = wid & 3;          // 4 warps along m (32 rows each)
    const int wn = wid >> 2;         // 2 warps along n (64 cols each)
    const int lrow = lane & 15;
    const int lcolb = (lane >> 4) * 16;
    const uint32_t lxor = ((uint32_t)(lrow & 7)) << 4;
    const int groupId = lane >> 2;
    const int tid4 = lane & 3;
    const float INFV = __int_as_float(0x7F800000);

    // triangular tile decode
    int t = blockIdx.x;
    int it = (int)floorf((129.0f - sqrtf(129.0f * 129.0f - 8.0f * (float)t)) * 0.5f);
    while (it > 0 && (it * (129 - it)) / 2 > t) it--;
    while (((it + 1) * (129 - (it + 1))) / 2 <= t) it++;
    const int jt = it + (t - (it * (129 - it)) / 2);
    const int iBase = it * 128;
    const int jBase = jt * 128;
    const bool dtile = (it == jt);

    const uint32_t sb = smem_u32(dsm);
    const uint32_t stage0 = (sb + 1023u) & ~1023u;
    const uint32_t stage1 = stage0 + STAGE_BYTES;

    if (tid < 128) {
        s_sqi[tid] = g_sq[iBase + tid];
        s_sqj[tid] = g_sq[jBase + tid];
        s_rowmin[tid] = FLTMAX_BITS;
        s_colmin[tid] = FLTMAX_BITS;
    }

    // fp16 accumulators: acc[mf][nf] = 2 regs (packed half2)
    uint32_t acc[2][8][2];
#pragma unroll
    for (int mf = 0; mf < 2; mf++)
#pragma unroll
        for (int nf = 0; nf < 8; nf++) { acc[mf][nf][0] = 0u; acc[mf][nf][1] = 0u; }

    load_chunk(stage0, iBase, jBase, 0, tid);
    load_chunk(stage1, iBase, jBase, 1, tid);

#pragma unroll 1
    for (int kc = 0; kc < 4; kc++) {
        const uint32_t stage = (kc & 1) ? stage1 : stage0;
        if (kc < 3) asm volatile("cp.async.wait_group 1;" ::: "memory");
        else        asm volatile("cp.async.wait_group 0;" ::: "memory");
        __syncthreads();   // all warps' copies landed AND prior compute done

        const uint32_t aB = stage + (uint32_t)(wm * 32 + lrow) * 128u;
        const uint32_t bB = stage + (uint32_t)TILE_BYTES
                          + (uint32_t)(wn * 64 + lrow) * 128u;

        // B fragments double-banked: prefetch ks+1 while MMAs consume ks
        uint32_t brP[4][4], brQ[4][4];
        {
            const uint32_t csw0 = ((uint32_t)lcolb) ^ lxor;
#pragma unroll
            for (int ng = 0; ng < 4; ng++)
                LDSM4(brP[ng], bB + (uint32_t)(ng * 16 * 128) + csw0);
        }
#pragma unroll
        for (int ks = 0; ks < 4; ks++) {
            if (ks < 3) {
                const uint32_t cswn = ((uint32_t)((ks + 1) * 32 + lcolb)) ^ lxor;
                if (ks & 1) {
#pragma unroll
                    for (int ng = 0; ng < 4; ng++)
                        LDSM4(brP[ng], bB + (uint32_t)(ng * 16 * 128) + cswn);
                } else {
#pragma unroll
                    for (int ng = 0; ng < 4; ng++)
                        LDSM4(brQ[ng], bB + (uint32_t)(ng * 16 * 128) + cswn);
                }
            }
            const uint32_t csw = ((uint32_t)(ks * 32 + lcolb)) ^ lxor;
#pragma unroll
            for (int mf = 0; mf < 2; mf++) {
                uint32_t af[4];
                LDSM4(af, aB + (uint32_t)(mf * 16 * 128) + csw);
                if (ks & 1) {
#pragma unroll
                    for (int ng = 0; ng < 4; ng++) {
                        MMA16816H(acc[mf][2 * ng],     af, brQ[ng][0], brQ[ng][2]);
                        MMA16816H(acc[mf][2 * ng + 1], af, brQ[ng][1], brQ[ng][3]);
                    }
                } else {
#pragma unroll
                    for (int ng = 0; ng < 4; ng++) {
                        MMA16816H(acc[mf][2 * ng],     af, brP[ng][0], brP[ng][2]);
                        MMA16816H(acc[mf][2 * ng + 1], af, brP[ng][1], brP[ng][3]);
                    }
                }
            }
        }
        __syncthreads();   // stage fully consumed by all warps
        if (kc + 2 < 4)
            load_chunk(stage, iBase, jBase, kc + 2, tid);
    }

    // ---------------- mining epilogue ----------------
    float rmin[2][2];    // [mf][rowhalf]
    float cmin[8][2];    // [nf][colparity]
#pragma unroll
    for (int mf = 0; mf < 2; mf++) { rmin[mf][0] = INFV; rmin[mf][1] = INFV; }
#pragma unroll
    for (int nf = 0; nf < 8; nf++) { cmin[nf][0] = INFV; cmin[nf][1] = INFV; }

#pragma unroll
    for (int mf = 0; mf < 2; mf++) {
#pragma unroll
        for (int nf = 0; nf < 8; nf++) {
            float2 h0 = __half22float2(*reinterpret_cast<__half2*>(&acc[mf][nf][0]));
            float2 h1 = __half22float2(*reinterpret_cast<__half2*>(&acc[mf][nf][1]));
            float dots[4] = {h0.x, h0.y, h1.x, h1.y};
#pragma unroll
            for (int r = 0; r < 4; r++) {
                const int row_l = wm * 32 + mf * 16 + groupId + (r >> 1) * 8;
                const int col_l = wn * 64 + nf * 8 + tid4 * 2 + (r & 1);
                float d2 = fmaf(dots[r], -2.0f, s_sqi[row_l]) + s_sqj[col_l];
                if (row_l == col_l) {
                    s_diag[row_l] = fmaxf(d2, 0.0f);
                } else {
                    rmin[mf][r >> 1] = fminf(rmin[mf][r >> 1], d2);
                    cmin[nf][r & 1]  = fminf(cmin[nf][r & 1], d2);
                }
            }
        }
    }

    // row reduce over tid4 (lanes sharing rows)
#pragma unroll
    for (int mf = 0; mf < 2; mf++) {
#pragma unroll
        for (int h = 0; h < 2; h++) {
            float v = rmin[mf][h];
            v = fminf(v, __shfl_xor_sync(0xFFFFFFFFu, v, 1));
            v = fminf(v, __shfl_xor_sync(0xFFFFFFFFu, v, 2));
            if (tid4 == 0)
                atomicMin(&s_rowmin[wm * 32 + mf * 16 + groupId + 8 * h], __float_as_int(v));
        }
    }
    // col reduce over groupId (lanes sharing cols)
#pragma unroll
    for (int nf = 0; nf < 8; nf++) {
#pragma unroll
        for (int par = 0; par < 2; par++) {
            float v = cmin[nf][par];
            v = fminf(v, __shfl_xor_sync(0xFFFFFFFFu, v, 4));
            v = fminf(v, __shfl_xor_sync(0xFFFFFFFFu, v, 8));
            v = fminf(v, __shfl_xor_sync(0xFFFFFFFFu, v, 16));
            if (groupId == 0)
                atomicMin(&s_colmin[wn * 64 + nf * 8 + tid4 * 2 + par], __float_as_int(v));
        }
    }
    __syncthreads();

    if (tid < 128) {
        const int row = iBase + tid;
        atomicMin(reinterpret_cast<int*>(&g_hn2[row]), s_rowmin[tid]);
        if (!dtile) {
            const int col = jBase + tid;
            atomicMin(reinterpret_cast<int*>(&g_hn2[col]), s_colmin[tid]);
            const int db = __float_as_int(s_diag[tid]);
            atomicMax(reinterpret_cast<int*>(&g_hp2[row]), db);
            atomicMax(reinterpret_cast<int*>(&g_hp2[col]), db);
        }
    }

    // ---- last CTA does the final reduction ----
    __threadfence();
    __syncthreads();
    if (tid == 0)
        s_last = (atomicAdd(&g_done, 1u) == NPAIRTILES - 1) ? 1u : 0u;
    __syncthreads();
    if (s_last) {
        __threadfence();
        float tsum = 0.0f;
        for (int i = tid; i < NROWS; i += NTHREADS) {
            float hp = sqrtf(fmaxf(g_hp2[i], 0.0f));
            float hn = sqrtf(fmaxf(g_hn2[i], 0.0f));
            tsum += fmaxf(hp - hn + MARGIN, 0.0f);
        }
        float msum = 0.0f;
        if (tid < BQ) {
            float g = gt[tid];
            float a = s0[tid] - g, b = s1[tid] - g, c = s2[tid] - g;
            msum = a * a + b * b + c * c;
        }
        float dsum = (tid < NDRBLK) ? g_dpart[tid] : 0.0f;

        float vals[3] = {tsum, msum, dsum};
        float res[3];
#pragma unroll
        for (int v = 0; v < 3; v++) {
            s_red[tid] = vals[v];
            __syncthreads();
            for (int st = NTHREADS / 2; st > 0; st >>= 1) {
                if (tid < st) s_red[tid] += s_red[tid + st];
                __syncthreads();
            }
            res[v] = s_red[0];
            __syncthreads();
        }
        if (tid == 0) {
            float t_loss = res[0] / (float)NROWS;
            float mse    = res[1] / (float)(BQ * 3);
            float dr     = res[2] / (float)DDIM;
            out[0] = dr + t_loss + mse;
        }
    }
}

// ---------------------------------------------------------------------------
extern "C" void kernel_launch(void* const* d_in, const int* in_sizes, int n_in,
                              void* d_out, int out_size) {
    const float* feat = (const float*)d_in[0];
    const float* gt   = (const float*)d_in[1];
    const float* s0   = (const float*)d_in[2];
    const float* s1   = (const float*)d_in[3];
    const float* s2   = (const float*)d_in[4];
    const float* e0   = (const float*)d_in[5];
    const float* e1   = (const float*)d_in[6];
    const float* l0   = (const float*)d_in[7];
    const float* l1   = (const float*)d_in[8];
    float* out = (float*)d_out;

    cudaFuncSetAttribute(pair_mma_kernel,
                         cudaFuncAttributeMaxDynamicSharedMemorySize, SMEM_DYN);

    prep_kernel<<<NPREPBLK + NDRBLK, 256>>>(feat, e0, e1, l0, l1);
    pair_mma_kernel<<<NPAIRTILES, NTHREADS, SMEM_DYN>>>(gt, s0, s1, s2, out);
}

// round 14
// speedup vs baseline: 1.2153x; 1.0264x over previous
#include <cuda_runtime.h>
#include <cuda_fp16.h>
#include <math.h>
#include <stdint.h>

// ---------------- problem constants ----------------
#define NROWS 8192      // b*n
#define CDIM  256
#define NTILES 64
#define NPAIRTILES 2080 // NTILES*(NTILES+1)/2
#define BQ    64
#define DDIM  65536
#define MARGIN 0.3f
#define FLTMAX_BITS 0x7F7FFFFF

#define NTHREADS 256               // 8 warps: 4 along m x 2 along n, 32x64 each
#define TILE_BYTES 16384           // 128 rows x 128B (64 fp16 cols)
#define STAGE_BYTES (2 * TILE_BYTES)  // A, B
#define SMEM_DYN (2 * STAGE_BYTES + 1024)
#define NDRBLK 64
#define NPREPBLK 1024              // 8 rows per block

// ---------------- device globals (no allocs allowed) ----------------
__device__ __align__(128) __half g_P[(size_t)NROWS * CDIM];
__device__ float g_sq[NROWS];
__device__ float g_hp2[NROWS];
__device__ float g_hn2[NROWS];
__device__ float g_dpart[NDRBLK];
__device__ unsigned g_done;

// ---------------- PTX helpers (baseline sm_80-class only) ----------------
__device__ __forceinline__ uint32_t smem_u32(const void* p) {
    uint32_t a;
    asm("{ .reg .u64 t; cvta.to.shared.u64 t, %1; cvt.u32.u64 %0, t; }" : "=r"(a) : "l"(p));
    return a;
}

#define CP_ASYNC16(dst, src) \
    asm volatile("cp.async.cg.shared.global [%0], [%1], 16;" :: "r"(dst), "l"(src) : "memory")
#define CP_COMMIT() asm volatile("cp.async.commit_group;" ::: "memory")

#define LDSM4(r, addr) \
    asm volatile("ldmatrix.sync.aligned.m8n8.x4.shared.b16 {%0,%1,%2,%3}, [%4];" \
        : "=r"((r)[0]), "=r"((r)[1]), "=r"((r)[2]), "=r"((r)[3]) : "r"(addr))

// fp16-accumulate MMA: D(2 regs packed half2) = A(4) x B(2) + D
#define MMA16816H(d, a, b0, b1) \
    asm volatile("mma.sync.aligned.m16n8k16.row.col.f16.f16.f16.f16 " \
        "{%0,%1}, {%2,%3,%4,%5}, {%6,%7}, {%0,%1};" \
        : "+r"((d)[0]), "+r"((d)[1]) \
        : "r"((a)[0]), "r"((a)[1]), "r"((a)[2]), "r"((a)[3]), "r"(b0), "r"(b1))

// ---------------------------------------------------------------------------
// Kernel 0 (fused): blocks [0,1024): fp16 convert + row norms (of ROUNDED
// values) + hp/hn reset. Blocks [1024,1088): dr (L1) partial sums.
// ---------------------------------------------------------------------------
__global__ void prep_kernel(const float* __restrict__ x,
                            const float* __restrict__ e0,
                            const float* __restrict__ e1,
                            const float* __restrict__ l0,
                            const float* __restrict__ l1) {
    const int tid = threadIdx.x;
    if (blockIdx.x == 0 && tid == 0) g_done = 0u;
    if (blockIdx.x < NPREPBLK) {
        const int wid = tid >> 5, lane = tid & 31;
        const int row = blockIdx.x * 8 + wid;
        const float4* xr = reinterpret_cast<const float4*>(x + (size_t)row * CDIM);
        float4 v0 = xr[lane * 2 + 0];
        float4 v1 = xr[lane * 2 + 1];
        float a[8] = {v0.x, v0.y, v0.z, v0.w, v1.x, v1.y, v1.z, v1.w};
        float s = 0.0f;
        unsigned hb[8];
#pragma unroll
        for (int i = 0; i < 8; i++) {
            __half h = __float2half_rn(a[i]);
            hb[i] = (unsigned)__half_as_ushort(h);
            float r = __half2float(h);
            s = fmaf(r, r, s);
        }
        uint4 ph = make_uint4(hb[0] | (hb[1] << 16), hb[2] | (hb[3] << 16),
                              hb[4] | (hb[5] << 16), hb[6] | (hb[7] << 16));
        *reinterpret_cast<uint4*>(&g_P[(size_t)row * CDIM + lane * 8]) = ph;
#pragma unroll
        for (int off = 16; off > 0; off >>= 1)
            s += __shfl_xor_sync(0xFFFFFFFFu, s, off);
        if (lane == 0) {
            g_sq[row]  = s;
            g_hp2[row] = 0.0f;
            g_hn2[row] = __int_as_float(FLTMAX_BITS);
        }
    } else {
        __shared__ float red[256];
        const int b = blockIdx.x - NPREPBLK;
        const int base = b * (DDIM / NDRBLK);
        float s = 0.0f;
#pragma unroll
        for (int k = 0; k < DDIM / NDRBLK / 256; k++) {
            int i = base + k * 256 + tid;
            s += fabsf(e0[i] - l0[i]) + fabsf(e1[i] - l1[i]);
        }
        red[tid] = s;
        __syncthreads();
        for (int st = 128; st > 0; st >>= 1) {
            if (tid < st) red[tid] += red[tid + st];
            __syncthreads();
        }
        if (tid == 0) g_dpart[b] = red[0];
    }
}

// ---------------------------------------------------------------------------
// Load one 64-col chunk kc into a stage: A (rows iBase..), B (rows jBase..).
// 256 threads x 8 cp.async x 16B, SW128 swizzle.
// ---------------------------------------------------------------------------
__device__ __forceinline__ void load_chunk(uint32_t stage, int iBase, int jBase,
                                           int kc, int tid) {
    const int cu = tid & 7;          // 16B column unit
    const int r0 = tid >> 3;         // 0..31
    const uint32_t colsw = ((uint32_t)(cu * 16)) ^ (((uint32_t)(r0 & 7)) << 4);
    const int ecol = kc * 64 + cu * 8;
#pragma unroll
    for (int i = 0; i < 4; i++) {
        const int row = r0 + 32 * i;
        const uint32_t dst = stage + (uint32_t)row * 128u + colsw;
        CP_ASYNC16(dst,              &g_P[(size_t)(iBase + row) * CDIM + ecol]); // A
        CP_ASYNC16(dst + TILE_BYTES, &g_P[(size_t)(jBase + row) * CDIM + ecol]); // B
    }
    CP_COMMIT();
}

// ---------------------------------------------------------------------------
// One k-chunk of MMAs from a given stage (banked B fragments).
// ---------------------------------------------------------------------------
__device__ __forceinline__ void mma_chunk(uint32_t stage, int wm, int wn,
                                          int lrow, int lcolb, uint32_t lxor,
                                          uint32_t acc[2][8][2]) {
    const uint32_t aB = stage + (uint32_t)(wm * 32 + lrow) * 128u;
    const uint32_t bB = stage + (uint32_t)TILE_BYTES
                      + (uint32_t)(wn * 64 + lrow) * 128u;
    uint32_t brP[4][4], brQ[4][4];
    {
        const uint32_t csw0 = ((uint32_t)lcolb) ^ lxor;
#pragma unroll
        for (int ng = 0; ng < 4; ng++)
            LDSM4(brP[ng], bB + (uint32_t)(ng * 16 * 128) + csw0);
    }
#pragma unroll
    for (int ks = 0; ks < 4; ks++) {
        if (ks < 3) {
            const uint32_t cswn = ((uint32_t)((ks + 1) * 32 + lcolb)) ^ lxor;
            if (ks & 1) {
#pragma unroll
                for (int ng = 0; ng < 4; ng++)
                    LDSM4(brP[ng], bB + (uint32_t)(ng * 16 * 128) + cswn);
            } else {
#pragma unroll
                for (int ng = 0; ng < 4; ng++)
                    LDSM4(brQ[ng], bB + (uint32_t)(ng * 16 * 128) + cswn);
            }
        }
        const uint32_t csw = ((uint32_t)(ks * 32 + lcolb)) ^ lxor;
#pragma unroll
        for (int mf = 0; mf < 2; mf++) {
            uint32_t af[4];
            LDSM4(af, aB + (uint32_t)(mf * 16 * 128) + csw);
            if (ks & 1) {
#pragma unroll
                for (int ng = 0; ng < 4; ng++) {
                    MMA16816H(acc[mf][2 * ng],     af, brQ[ng][0], brQ[ng][2]);
                    MMA16816H(acc[mf][2 * ng + 1], af, brQ[ng][1], brQ[ng][3]);
                }
            } else {
#pragma unroll
                for (int ng = 0; ng < 4; ng++) {
                    MMA16816H(acc[mf][2 * ng],     af, brP[ng][0], brP[ng][2]);
                    MMA16816H(acc[mf][2 * ng + 1], af, brP[ng][1], brP[ng][3]);
                }
            }
        }
    }
}

// ---------------------------------------------------------------------------
// Kernel 1: warp-MMA fused Gram + mining, one 128x128 tile (it<=jt) per CTA.
// 8 warps (4m x 2n), 32x64 warp tile, fp16 MMA/acc, 3 CTAs/SM.
// Fully unrolled kc pipeline; register-resident norms; diag-specialized
// epilogue. Last CTA performs the final scalar reduction.
// ---------------------------------------------------------------------------
__global__ void __launch_bounds__(NTHREADS, 3)
pair_mma_kernel(const float* __restrict__ gt,
                const float* __restrict__ s0,
                const float* __restrict__ s1,
                const float* __restrict__ s2,
                float* __restrict__ out) {
    extern __shared__ __align__(16) char dsm[];
    __shared__ float s_sqi[128], s_sqj[128], s_diag[128];
    __shared__ int s_rowmin[128], s_colmin[128];
    __shared__ float s_red[NTHREADS];
    __shared__ unsigned s_last;

    const int tid = threadIdx.x;
    const int wid = tid >> 5;
    const int lane = tid & 31;
    const int wm = wid & 3;          // 4 warps along m (32 rows each)
    const int wn = wid >> 2;         // 2 warps along n (64 cols each)
    const int lrow = lane & 15;
    const int lcolb = (lane >> 4) * 16;
    const uint32_t lxor = ((uint32_t)(lrow & 7)) << 4;
    const int groupId = lane >> 2;
    const int tid4 = lane & 3;
    const float INFV = __int_as_float(0x7F800000);

    // triangular tile decode
    int t = blockIdx.x;
    int it = (int)floorf((129.0f - sqrtf(129.0f * 129.0f - 8.0f * (float)t)) * 0.5f);
    while (it > 0 && (it * (129 - it)) / 2 > t) it--;
    while (((it + 1) * (129 - (it + 1))) / 2 <= t) it++;
    const int jt = it + (t - (it * (129 - it)) / 2);
    const int iBase = it * 128;
    const int jBase = jt * 128;
    const bool dtile = (it == jt);

    const uint32_t sb = smem_u32(dsm);
    const uint32_t stage0 = (sb + 1023u) & ~1023u;
    const uint32_t stage1 = stage0 + STAGE_BYTES;

    if (tid < 128) {
        s_sqi[tid] = g_sq[iBase + tid];
        s_sqj[tid] = g_sq[jBase + tid];
        s_rowmin[tid] = FLTMAX_BITS;
        s_colmin[tid] = FLTMAX_BITS;
    }

    // fp16 accumulators: acc[mf][nf] = 2 regs (packed half2)
    uint32_t acc[2][8][2];
#pragma unroll
    for (int mf = 0; mf < 2; mf++)
#pragma unroll
        for (int nf = 0; nf < 8; nf++) { acc[mf][nf][0] = 0u; acc[mf][nf][1] = 0u; }

    load_chunk(stage0, iBase, jBase, 0, tid);
    load_chunk(stage1, iBase, jBase, 1, tid);

    // -------- fully unrolled 4-chunk pipeline (R13 sync order) --------
    asm volatile("cp.async.wait_group 1;" ::: "memory");
    __syncthreads();
    mma_chunk(stage0, wm, wn, lrow, lcolb, lxor, acc);
    __syncthreads();
    load_chunk(stage0, iBase, jBase, 2, tid);

    asm volatile("cp.async.wait_group 1;" ::: "memory");
    __syncthreads();
    mma_chunk(stage1, wm, wn, lrow, lcolb, lxor, acc);
    __syncthreads();
    load_chunk(stage1, iBase, jBase, 3, tid);

    asm volatile("cp.async.wait_group 1;" ::: "memory");
    __syncthreads();
    mma_chunk(stage0, wm, wn, lrow, lcolb, lxor, acc);

    asm volatile("cp.async.wait_group 0;" ::: "memory");
    __syncthreads();
    mma_chunk(stage1, wm, wn, lrow, lcolb, lxor, acc);

    // ---------------- mining epilogue (register-resident norms) ----------
    float sqi_r[2][2];   // [mf][h]
#pragma unroll
    for (int mf = 0; mf < 2; mf++)
#pragma unroll
        for (int h = 0; h < 2; h++)
            sqi_r[mf][h] = s_sqi[wm * 32 + mf * 16 + groupId + 8 * h];
    float sqj_r[8][2];   // [nf][par]
#pragma unroll
    for (int nf = 0; nf < 8; nf++)
#pragma unroll
        for (int par = 0; par < 2; par++)
            sqj_r[nf][par] = s_sqj[wn * 64 + nf * 8 + tid4 * 2 + par];

    float rmin[2][2];    // [mf][rowhalf]
    float cmin[8][2];    // [nf][colparity]
#pragma unroll
    for (int mf = 0; mf < 2; mf++) { rmin[mf][0] = INFV; rmin[mf][1] = INFV; }
#pragma unroll
    for (int nf = 0; nf < 8; nf++) { cmin[nf][0] = INFV; cmin[nf][1] = INFV; }

    if ((wm >> 1) == wn) {
        // this warp's tile intersects the block diagonal
#pragma unroll
        for (int mf = 0; mf < 2; mf++) {
#pragma unroll
            for (int nf = 0; nf < 8; nf++) {
                float2 h0 = __half22float2(*reinterpret_cast<__half2*>(&acc[mf][nf][0]));
                float2 h1 = __half22float2(*reinterpret_cast<__half2*>(&acc[mf][nf][1]));
                float dots[4] = {h0.x, h0.y, h1.x, h1.y};
#pragma unroll
                for (int r = 0; r < 4; r++) {
                    const int row_l = wm * 32 + mf * 16 + groupId + (r >> 1) * 8;
                    const int col_l = wn * 64 + nf * 8 + tid4 * 2 + (r & 1);
                    float d2 = fmaf(dots[r], -2.0f, sqi_r[mf][r >> 1]) + sqj_r[nf][r & 1];
                    if (row_l == col_l) {
                        s_diag[row_l] = fmaxf(d2, 0.0f);
                    } else {
                        rmin[mf][r >> 1] = fminf(rmin[mf][r >> 1], d2);
                        cmin[nf][r & 1]  = fminf(cmin[nf][r & 1], d2);
                    }
                }
            }
        }
    } else {
        // no diagonal elements: unconditional mining
#pragma unroll
        for (int mf = 0; mf < 2; mf++) {
#pragma unroll
            for (int nf = 0; nf < 8; nf++) {
                float2 h0 = __half22float2(*reinterpret_cast<__half2*>(&acc[mf][nf][0]));
                float2 h1 = __half22float2(*reinterpret_cast<__half2*>(&acc[mf][nf][1]));
                float dots[4] = {h0.x, h0.y, h1.x, h1.y};
#pragma unroll
                for (int r = 0; r < 4; r++) {
                    float d2 = fmaf(dots[r], -2.0f, sqi_r[mf][r >> 1]) + sqj_r[nf][r & 1];
                    rmin[mf][r >> 1] = fminf(rmin[mf][r >> 1], d2);
                    cmin[nf][r & 1]  = fminf(cmin[nf][r & 1], d2);
                }
            }
        }
    }

    // row reduce over tid4 (lanes sharing rows)
#pragma unroll
    for (int mf = 0; mf < 2; mf++) {
#pragma unroll
        for (int h = 0; h < 2; h++) {
            float v = rmin[mf][h];
            v = fminf(v, __shfl_xor_sync(0xFFFFFFFFu, v, 1));
            v = fminf(v, __shfl_xor_sync(0xFFFFFFFFu, v, 2));
            if (tid4 == 0)
                atomicMin(&s_rowmin[wm * 32 + mf * 16 + groupId + 8 * h], __float_as_int(v));
        }
    }
    // col reduce over groupId (lanes sharing cols)
#pragma unroll
    for (int nf = 0; nf < 8; nf++) {
#pragma unroll
        for (int par = 0; par < 2; par++) {
            float v = cmin[nf][par];
            v = fminf(v, __shfl_xor_sync(0xFFFFFFFFu, v, 4));
            v = fminf(v, __shfl_xor_sync(0xFFFFFFFFu, v, 8));
            v = fminf(v, __shfl_xor_sync(0xFFFFFFFFu, v, 16));
            if (groupId == 0)
                atomicMin(&s_colmin[wn * 64 + nf * 8 + tid4 * 2 + par], __float_as_int(v));
        }
    }
    __syncthreads();

    if (tid < 128) {
        const int row = iBase + tid;
        atomicMin(reinterpret_cast<int*>(&g_hn2[row]), s_rowmin[tid]);
        if (!dtile) {
            const int col = jBase + tid;
            atomicMin(reinterpret_cast<int*>(&g_hn2[col]), s_colmin[tid]);
            const int db = __float_as_int(s_diag[tid]);
            atomicMax(reinterpret_cast<int*>(&g_hp2[row]), db);
            atomicMax(reinterpret_cast<int*>(&g_hp2[col]), db);
        }
    }

    // ---- last CTA does the final reduction ----
    __threadfence();
    __syncthreads();
    if (tid == 0)
        s_last = (atomicAdd(&g_done, 1u) == NPAIRTILES - 1) ? 1u : 0u;
    __syncthreads();
    if (s_last) {
        __threadfence();
        float tsum = 0.0f;
        for (int i = tid; i < NROWS; i += NTHREADS) {
            float hp = sqrtf(fmaxf(g_hp2[i], 0.0f));
            float hn = sqrtf(fmaxf(g_hn2[i], 0.0f));
            tsum += fmaxf(hp - hn + MARGIN, 0.0f);
        }
        float msum = 0.0f;
        if (tid < BQ) {
            float g = gt[tid];
            float a = s0[tid] - g, b = s1[tid] - g, c = s2[tid] - g;
            msum = a * a + b * b + c * c;
        }
        float dsum = (tid < NDRBLK) ? g_dpart[tid] : 0.0f;

        float vals[3] = {tsum, msum, dsum};
        float res[3];
#pragma unroll
        for (int v = 0; v < 3; v++) {
            s_red[tid] = vals[v];
            __syncthreads();
            for (int st = NTHREADS / 2; st > 0; st >>= 1) {
                if (tid < st) s_red[tid] += s_red[tid + st];
                __syncthreads();
            }
            res[v] = s_red[0];
            __syncthreads();
        }
        if (tid == 0) {
            float t_loss = res[0] / (float)NROWS;
            float mse    = res[1] / (float)(BQ * 3);
            float dr     = res[2] / (float)DDIM;
            out[0] = dr + t_loss + mse;
        }
    }
}

// ---------------------------------------------------------------------------
extern "C" void kernel_launch(void* const* d_in, const int* in_sizes, int n_in,
                              void* d_out, int out_size) {
    const float* feat = (const float*)d_in[0];
    const float* gt   = (const float*)d_in[1];
    const float* s0   = (const float*)d_in[2];
    const float* s1   = (const float*)d_in[3];
    const float* s2   = (const float*)d_in[4];
    const float* e0   = (const float*)d_in[5];
    const float* e1   = (const float*)d_in[6];
    const float* l0   = (const float*)d_in[7];
    const float* l1   = (const float*)d_in[8];
    float* out = (float*)d_out;

    cudaFuncSetAttribute(pair_mma_kernel,
                         cudaFuncAttributeMaxDynamicSharedMemorySize, SMEM_DYN);

    prep_kernel<<<NPREPBLK + NDRBLK, 256>>>(feat, e0, e1, l0, l1);
    pair_mma_kernel<<<NPAIRTILES, NTHREADS, SMEM_DYN>>>(gt, s0, s1, s2, out);
}